// round 12
// baseline (speedup 1.0000x reference)
#include <cuda_runtime.h>
#include <cuda_fp16.h>
#include <cstdint>

// Mean-shift as unnormalized attention, single persistent kernel.
//   S = (sX)^T (sX), s^2 = 2*log2(e)  =>  P = ex2(S) = exp(2*x_i.x_j)
//   GEMM1: FP8 e4m3 mma m16n8k32 (half the mma count of f16 k16), f32 accum.
//   P = ex2.f16x2(cvt(S)); deg = P @ ones (tensor); O = P @ V (f16 tensor).
// Free-running warp pairs with private 3-stage K/V rings (named barriers only).

#define NPTS   9216
#define DIM    32
#define ETA    0.5f
#define SCALE  1.6986436f          // sqrt(2*log2(e))
#define TJ     64
#define TI     64
#define KSPLIT 4
#define JT     (NPTS / TJ)             // 144
#define NT     (NPTS / (TI * KSPLIT))  // 36 tiles per split
#define GRID   (JT * KSPLIT)           // 576
#define FRAME  (DIM * NPTS)

#define ONES2 0x3C003C00u

// pair ring stage: K fp8 32x48B = 1536, V f16 32x80B = 2560 -> 4096
#define KROWST 48              // fp8 key row stride (12 banks: conflict-free)
#define VROWST 80
#define VOFF  1536
#define STG   4096
#define RING  (3 * STG)        // 12288 per pair
#define SMEM_BYTES (2 * RING)  // 24576
#define SH_X 0                 // O exchange (8KB), aliases pair-0 ring
#define SH_XD 8192             // deg exchange (1KB)

__device__ __align__(16) uint8_t g_s8[NPTS * DIM];   // [i][d] e4m3, scaled
__device__ __align__(16) __half  g_v[DIM * NPTS];    // [d][i] f16
__device__ float g_accum[KSPLIT][DIM][NPTS];
__device__ float g_degp[KSPLIT][NPTS];
__device__ unsigned g_bar;
__device__ unsigned g_fin;

// ---------------- helpers ----------------
__device__ __forceinline__ uint32_t smem_u32(const void* p) {
    uint32_t a;
    asm("{ .reg .u64 t; cvta.to.shared.u64 t, %1; cvt.u32.u64 %0, t; }" : "=r"(a) : "l"(p));
    return a;
}
__device__ __forceinline__ void ldsm4(uint32_t* r, uint32_t a) {
    asm volatile("ldmatrix.sync.aligned.m8n8.x4.shared.b16 {%0,%1,%2,%3}, [%4];"
        : "=r"(r[0]), "=r"(r[1]), "=r"(r[2]), "=r"(r[3]) : "r"(a));
}
__device__ __forceinline__ uint32_t lds32(uint32_t a) {
    uint32_t r;
    asm volatile("ld.shared.b32 %0, [%1];" : "=r"(r) : "r"(a));
    return r;
}
// f16 mma, fp32 accum (GEMM2 / deg)
__device__ __forceinline__ void mma16816(float* c, const uint32_t* a,
                                         uint32_t b0, uint32_t b1) {
    asm volatile("mma.sync.aligned.m16n8k16.row.col.f32.f16.f16.f32 "
        "{%0,%1,%2,%3}, {%4,%5,%6,%7}, {%8,%9}, {%0,%1,%2,%3};"
        : "+f"(c[0]), "+f"(c[1]), "+f"(c[2]), "+f"(c[3])
        : "r"(a[0]), "r"(a[1]), "r"(a[2]), "r"(a[3]), "r"(b0), "r"(b1));
}
// fp8 e4m3 mma, K=32, fp32 accum (GEMM1)
__device__ __forceinline__ void mma16832f8(float* c, const uint32_t* a,
                                           uint32_t b0, uint32_t b1) {
    asm volatile("mma.sync.aligned.m16n8k32.row.col.f32.e4m3.e4m3.f32 "
        "{%0,%1,%2,%3}, {%4,%5,%6,%7}, {%8,%9}, {%0,%1,%2,%3};"
        : "+f"(c[0]), "+f"(c[1]), "+f"(c[2]), "+f"(c[3])
        : "r"(a[0]), "r"(a[1]), "r"(a[2]), "r"(a[3]), "r"(b0), "r"(b1));
}
__device__ __forceinline__ uint32_t cvt_f16x2(float lo, float hi) {
    uint32_t r;
    asm("cvt.rn.f16x2.f32 %0, %1, %2;" : "=r"(r) : "f"(hi), "f"(lo));
    return r;
}
__device__ __forceinline__ uint16_t cvt_e4m3x2(float lo, float hi) {
    uint16_t r;
    asm("cvt.rn.satfinite.e4m3x2.f32 %0, %1, %2;" : "=h"(r) : "f"(hi), "f"(lo));
    return r;
}
__device__ __forceinline__ uint32_t pack16(uint16_t lo, uint16_t hi) {
    uint32_t r;
    asm("mov.b32 %0, {%1, %2};" : "=r"(r) : "h"(lo), "h"(hi));
    return r;
}
__device__ __forceinline__ uint32_t ex2_h2(uint32_t x) {
    uint32_t y;
    asm("ex2.approx.f16x2 %0, %1;" : "=r"(y) : "r"(x));
    return y;
}
#define CP16(dst, src) asm volatile("cp.async.cg.shared.global [%0], [%1], 16;" :: "r"(dst), "l"(src) : "memory")
#define CP_COMMIT()    asm volatile("cp.async.commit_group;" ::: "memory")
#define CP_WAIT0()     asm volatile("cp.async.wait_group 0;" ::: "memory")
#define CP_WAIT1()     asm volatile("cp.async.wait_group 1;" ::: "memory")
#define BAR_PAIR(wk)   asm volatile("bar.sync %0, 64;" :: "r"(1 + (wk)) : "memory")

__device__ __forceinline__ void grid_bar(unsigned tgt) {
    __syncthreads();
    __threadfence();
    if (threadIdx.x == 0) {
        atomicAdd(&g_bar, 1u);
        while (*(volatile unsigned*)&g_bar < tgt) __nanosleep(32);
    }
    __syncthreads();
}

// Stage one 32-key K/V slice for this pair (64 threads, 3 CP16 each).
__device__ __forceinline__ void stage_pair(uint32_t dst, int i0w, int ptid) {
    const char* gk = reinterpret_cast<const char*>(g_s8) + (size_t)i0w * DIM;
    {   // K fp8: 32 rows x 32B = 64 chunks
        int row = ptid >> 1, c = ptid & 1;
        CP16(dst + row * KROWST + c * 16, gk + row * 32 + c * 16);
    }
    const char* gv = reinterpret_cast<const char*>(g_v) + (size_t)i0w * 2;
#pragma unroll
    for (int cc = 0; cc < 2; cc++) {   // V f16: 32 d-rows x 64B = 128 chunks
        int idx = cc * 64 + ptid, d = idx >> 2, c = idx & 3;
        CP16(dst + VOFF + d * VROWST + c * 16, gv + (size_t)d * (NPTS * 2) + c * 16);
    }
}

__global__ void __launch_bounds__(128, 4)
ms_persist(const float* __restrict__ x_in, float* __restrict__ out) {
    __shared__ __align__(16) uint8_t sm[SMEM_BYTES];

    const int tid = threadIdx.x, w = tid >> 5, lane = tid & 31;
    const int wq = w >> 1, wk = w & 1;
    const int ptid = wq * 32 + lane;
    const int jt = blockIdx.x, split = blockIdx.y;
    const unsigned gid = (blockIdx.y * JT + blockIdx.x) * 128u + tid;
    const uint32_t smbase = smem_u32(sm);
    const uint32_t rb = smbase + (uint32_t)wk * RING;
    unsigned tgt = 0;

    // ---------------- phase 0: init (4 threads per pixel) ----------------
    if (gid < NPTS * 4u) {
        const int j = gid >> 2, d0 = (gid & 3) * 8;
        uint16_t h8[4];
#pragma unroll
        for (int q = 0; q < 4; q++) {
            int d = d0 + q * 2;
            float x0 = x_in[d * NPTS + j];
            float x1 = x_in[(d + 1) * NPTS + j];
            out[d * NPTS + j] = x0;
            out[(d + 1) * NPTS + j] = x1;
            g_v[d * NPTS + j] = __float2half(x0);
            g_v[(d + 1) * NPTS + j] = __float2half(x1);
            h8[q] = cvt_e4m3x2(x0 * SCALE, x1 * SCALE);
        }
        uint2 pk2 = make_uint2(pack16(h8[0], h8[1]), pack16(h8[2], h8[3]));
        *reinterpret_cast<uint2*>(g_s8 + (size_t)j * DIM + d0) = pk2;
    }
    tgt += GRID; grid_bar(tgt);

    // hoisted shared addresses within a ring stage (add bc*STG per tile)
    uint32_t ka0[4], va0[4];
#pragma unroll
    for (int nt = 0; nt < 4; nt++)
        ka0[nt] = rb + (nt * 8 + (lane >> 2)) * KROWST + (lane & 3) * 4;
#pragma unroll
    for (int dt = 0; dt < 4; dt++)
        va0[dt] = rb + VOFF + (dt * 8 + (lane & 7)) * VROWST + (lane >> 3) * 16;

    for (int t = 0; t < 3; t++) {
        // ---------------- attention phase ----------------
        const int j0 = jt * TJ;
        // stage Q fp8 tile (64 rows x 32B, 48B stride) at smem offset 0
        {
            int row = tid >> 1, c = tid & 1;
            const uint4* src = reinterpret_cast<const uint4*>(
                g_s8 + (size_t)(j0 + row) * DIM + c * 16);
            uint4 val = __ldcg(src);
            *reinterpret_cast<uint4*>(&sm[row * KROWST + c * 16]) = val;
        }
        __syncthreads();
        // Q fp8 A-fragments (m16n8k32): 2 mtiles x 4 regs
        uint32_t qa[8];
        {
            int r = lane >> 2, c4 = (lane & 3) * 4;
#pragma unroll
            for (int mt = 0; mt < 2; mt++) {
                uint32_t base = smbase + (wq * 32 + mt * 16 + r) * KROWST + c4;
                qa[mt * 4 + 0] = lds32(base);
                qa[mt * 4 + 1] = lds32(base + 8 * KROWST);
                qa[mt * 4 + 2] = lds32(base + 16);
                qa[mt * 4 + 3] = lds32(base + 8 * KROWST + 16);
            }
        }
        __syncthreads();   // Q reads done before rings are overwritten

        float O[32];
#pragma unroll
        for (int i = 0; i < 32; i++) O[i] = 0.0f;
        float dacc[8];
#pragma unroll
        for (int i = 0; i < 8; i++) dacc[i] = 0.0f;

        const int i00 = split * (NPTS / KSPLIT) + wk * 32;
        stage_pair(rb,       i00,      ptid); CP_COMMIT();
        stage_pair(rb + STG, i00 + TI, ptid); CP_COMMIT();

        int bc = 0;
        for (int it = 0; it < NT; it++) {
            if (it + 1 < NT) { CP_WAIT1(); } else { CP_WAIT0(); }
            BAR_PAIR(wk);
            const uint32_t ofs = (uint32_t)bc * STG;

            // GEMM1 (fp8, K=32 in one mma): S[2 x 16 rows][32 keys]
            float s[32];
#pragma unroll
            for (int x = 0; x < 32; x++) s[x] = 0.0f;
#pragma unroll
            for (int nt = 0; nt < 4; nt++) {
                uint32_t kb0 = lds32(ka0[nt] + ofs);
                uint32_t kb1 = lds32(ka0[nt] + ofs + 16);
                mma16832f8(&s[nt * 4],      qa,     kb0, kb1);
                mma16832f8(&s[16 + nt * 4], qa + 4, kb0, kb1);
            }

            // P = ex2(S) as f16x2 pairs -> A-fragments for GEMM2
            uint32_t pf[16];
#pragma unroll
            for (int mt = 0; mt < 2; mt++) {
#pragma unroll
                for (int kh = 0; kh < 2; kh++) {
                    const float* sa = &s[mt * 16 + kh * 8];
                    uint32_t* pa = &pf[mt * 8 + kh * 4];
                    pa[0] = ex2_h2(cvt_f16x2(sa[0], sa[1]));
                    pa[1] = ex2_h2(cvt_f16x2(sa[2], sa[3]));
                    pa[2] = ex2_h2(cvt_f16x2(sa[4], sa[5]));
                    pa[3] = ex2_h2(cvt_f16x2(sa[6], sa[7]));
                }
            }

            // deg += P @ ones (tensor, fp32, deterministic)
#pragma unroll
            for (int mt = 0; mt < 2; mt++) {
                mma16816(&dacc[mt * 4], &pf[mt * 8],     ONES2, ONES2);
                mma16816(&dacc[mt * 4], &pf[mt * 8 + 4], ONES2, ONES2);
            }

            // GEMM2: O[2 x 16 rows][32 d] += P x V
#pragma unroll
            for (int dt = 0; dt < 4; dt++) {
                uint32_t vb[4];
                ldsm4(vb, va0[dt] + ofs);
                mma16816(&O[dt * 4],      &pf[0],  vb[0], vb[1]);
                mma16816(&O[dt * 4],      &pf[4],  vb[2], vb[3]);
                mma16816(&O[16 + dt * 4], &pf[8],  vb[0], vb[1]);
                mma16816(&O[16 + dt * 4], &pf[12], vb[2], vb[3]);
            }

            // prefetch tile it+2 into stage (it+2)%3
            if (it + 2 < NT) {
                int bt = bc + 2; if (bt >= 3) bt -= 3;
                stage_pair(rb + (uint32_t)bt * STG, i00 + (it + 2) * TI, ptid);
                CP_COMMIT();
            }
            bc++; if (bc == 3) bc = 0;
        }

        // ---- cross-warp (wk) reduction of O and deg via smem ----
        __syncthreads();   // all warps done with rings (SH_X aliases them)
        if (wk == 1) {
#pragma unroll
            for (int r4 = 0; r4 < 8; r4++)
                *reinterpret_cast<float4*>(&sm[SH_X + wq * 4096 + r4 * 512 + lane * 16]) =
                    make_float4(O[r4 * 4], O[r4 * 4 + 1], O[r4 * 4 + 2], O[r4 * 4 + 3]);
            *reinterpret_cast<float2*>(&sm[SH_XD + wq * 512 + lane * 8]) =
                make_float2(dacc[0], dacc[2]);
            *reinterpret_cast<float2*>(&sm[SH_XD + wq * 512 + 256 + lane * 8]) =
                make_float2(dacc[4], dacc[6]);
        }
        __syncthreads();
        if (wk == 0) {
#pragma unroll
            for (int r4 = 0; r4 < 8; r4++) {
                float4 pv = *reinterpret_cast<const float4*>(
                    &sm[SH_X + wq * 4096 + r4 * 512 + lane * 16]);
                O[r4 * 4]     += pv.x;
                O[r4 * 4 + 1] += pv.y;
                O[r4 * 4 + 2] += pv.z;
                O[r4 * 4 + 3] += pv.w;
            }
            float2 p0 = *reinterpret_cast<const float2*>(&sm[SH_XD + wq * 512 + lane * 8]);
            float2 p1 = *reinterpret_cast<const float2*>(&sm[SH_XD + wq * 512 + 256 + lane * 8]);
            dacc[0] += p0.x; dacc[2] += p0.y;
            dacc[4] += p1.x; dacc[6] += p1.y;

#pragma unroll
            for (int mt = 0; mt < 2; mt++) {
                const int jj = j0 + wq * 32 + mt * 16 + (lane >> 2);
#pragma unroll
                for (int dt = 0; dt < 4; dt++) {
                    int d0 = dt * 8 + 2 * (lane & 3);
                    g_accum[split][d0][jj]         = O[mt * 16 + dt * 4 + 0];
                    g_accum[split][d0 + 1][jj]     = O[mt * 16 + dt * 4 + 1];
                    g_accum[split][d0][jj + 8]     = O[mt * 16 + dt * 4 + 2];
                    g_accum[split][d0 + 1][jj + 8] = O[mt * 16 + dt * 4 + 3];
                }
                if ((lane & 3) == 0) {
                    g_degp[split][jj]     = dacc[mt * 4 + 0];
                    g_degp[split][jj + 8] = dacc[mt * 4 + 2];
                }
            }
        }
        tgt += GRID; grid_bar(tgt);

        // ---------------- reduce phase (4 threads per pixel) ----------------
        if (gid < NPTS * 4u) {
            const int j = gid >> 2, d0 = (gid & 3) * 8;
            float deg = 0.0f;
#pragma unroll
            for (int sp = 0; sp < KSPLIT; sp++) deg += __ldcg(&g_degp[sp][j]);
            const float inv = ETA / deg;
            const float* X  = out + (size_t)t * FRAME;
            float*       Xn = out + (size_t)(t + 1) * FRAME;
            uint16_t h8[4];
#pragma unroll
            for (int q = 0; q < 4; q++) {
                int d = d0 + q * 2;
                float a0 = 0.0f, a1 = 0.0f;
#pragma unroll
                for (int sp = 0; sp < KSPLIT; sp++) {
                    a0 += __ldcg(&g_accum[sp][d][j]);
                    a1 += __ldcg(&g_accum[sp][d + 1][j]);
                }
                float x0 = a0 * inv + (1.0f - ETA) * X[d * NPTS + j];
                float x1 = a1 * inv + (1.0f - ETA) * X[(d + 1) * NPTS + j];
                Xn[d * NPTS + j] = x0;
                Xn[(d + 1) * NPTS + j] = x1;
                if (t < 2) {
                    g_v[d * NPTS + j] = __float2half(x0);
                    g_v[(d + 1) * NPTS + j] = __float2half(x1);
                    h8[q] = cvt_e4m3x2(x0 * SCALE, x1 * SCALE);
                }
            }
            if (t < 2) {
                uint2 pk2 = make_uint2(pack16(h8[0], h8[1]), pack16(h8[2], h8[3]));
                *reinterpret_cast<uint2*>(g_s8 + (size_t)j * DIM + d0) = pk2;
            }
        }
        if (t < 2) { tgt += GRID; grid_bar(tgt); }
    }

    // ---------------- epilogue: counter reset handshake ----------------
    __syncthreads();
    __threadfence();
    if (tid == 0) atomicAdd(&g_fin, 1u);
    if (gid == 0) {
        while (*(volatile unsigned*)&g_fin < GRID) __nanosleep(64);
        *(volatile unsigned*)&g_bar = 0;
        *(volatile unsigned*)&g_fin = 0;
        __threadfence();
    }
}

extern "C" void kernel_launch(void* const* d_in, const int* in_sizes, int n_in,
                              void* d_out, int out_size) {
    const float* x_in = (const float*)d_in[0];
    float* out = (float*)d_out;
    dim3 grid(JT, KSPLIT);
    ms_persist<<<grid, 128>>>(x_in, out);
}